// round 3
// baseline (speedup 1.0000x reference)
#include <cuda_runtime.h>
#include <math.h>

#define N_JOINTS 50
#define ROW 150
#define ROWS_PER_BLK 32
#define THREADS 256
#define TOTAL_ROWS (128 * 1024)
#define N_BLOCKS (TOTAL_ROWS / ROWS_PER_BLK)      // 4096
#define ELEMS (ROWS_PER_BLK * ROW)                // 4800 floats per tensor per block
#define VECS (ELEMS / 4)                          // 1200 float4
#define TINY 1.17549435082228750797e-38f

// Per-block partials, fully overwritten every launch.
__device__ float g_part_abs[N_BLOCKS];
__device__ float g_part_sq[N_BLOCKS];
// Completion counter: atomicInc wraps to 0 after N_BLOCKS increments ->
// deterministic state across graph replays, no zeroing kernel required.
__device__ unsigned int g_count = 0;

__global__ __launch_bounds__(THREADS) void bone_loss_kernel(
    const float* __restrict__ preds,
    const float* __restrict__ targets,
    float* __restrict__ out)
{
    __shared__ float sp[ELEMS];
    __shared__ float st[ELEMS];
    __shared__ float s_abs[THREADS / 32];
    __shared__ float s_sq[THREADS / 32];
    __shared__ bool s_last;

    const int tid = threadIdx.x;
    const int wid = tid >> 5;
    const int lid = tid & 31;

    // ---- Phase 1: vectorized streaming load + mask + stage to SMEM + L1 term ----
    const long long vbase = (long long)blockIdx.x * VECS;
    const float4* __restrict__ p4 = (const float4*)preds + vbase;
    const float4* __restrict__ t4 = (const float4*)targets + vbase;
    float4* sp4 = (float4*)sp;
    float4* st4 = (float4*)st;

    float abs_sum = 0.0f;
    #pragma unroll
    for (int i = tid; i < VECS; i += THREADS) {
        float4 t = __ldcs(t4 + i);   // evict-first: touched exactly once
        float4 p = __ldcs(p4 + i);
        float4 pm, tm;
        pm.x = (t.x != 0.0f) ? p.x : 0.0f;  tm.x = t.x;  // t already 0 where masked
        pm.y = (t.y != 0.0f) ? p.y : 0.0f;  tm.y = t.y;
        pm.z = (t.z != 0.0f) ? p.z : 0.0f;  tm.z = t.z;
        pm.w = (t.w != 0.0f) ? p.w : 0.0f;  tm.w = t.w;
        sp4[i] = pm;
        st4[i] = tm;
        abs_sum += fabsf(pm.x - tm.x) + fabsf(pm.y - tm.y)
                 + fabsf(pm.z - tm.z) + fabsf(pm.w - tm.w);
    }
    __syncthreads();

    // ---- Phase 2: per-bone direction terms (warp handles 4 rows) ----
    float sq_sum = 0.0f;
    #pragma unroll
    for (int r = 0; r < 4; r++) {
        const int roff = (wid * 4 + r) * ROW;
        for (int bi = lid; bi < N_JOINTS; bi += 32) {
            const int a = roff + 3 * bi;
            const int b = roff + 3 * ((bi + 1 == N_JOINTS) ? 0 : (bi + 1));

            float pd0 = sp[a]     - sp[b];
            float pd1 = sp[a + 1] - sp[b + 1];
            float pd2 = sp[a + 2] - sp[b + 2];
            float ta0 = st[a], ta1 = st[a + 1], ta2 = st[a + 2];
            float td0 = ta0 - st[b];
            float td1 = ta1 - st[b + 1];
            float td2 = ta2 - st[b + 2];

            float plen = sqrtf(fmaf(pd0, pd0, fmaf(pd1, pd1, pd2 * pd2)));
            float tlen = sqrtf(fmaf(td0, td0, fmaf(td1, td1, td2 * td2)));
            float pinv = 1.0f / (plen + TINY);
            float tinv = 1.0f / (tlen + TINY);

            float d0 = (ta0 != 0.0f) ? (pd0 * pinv - td0 * tinv) : 0.0f;
            float d1 = (ta1 != 0.0f) ? (pd1 * pinv - td1 * tinv) : 0.0f;
            float d2 = (ta2 != 0.0f) ? (pd2 * pinv - td2 * tinv) : 0.0f;

            sq_sum = fmaf(d0, d0, sq_sum);
            sq_sum = fmaf(d1, d1, sq_sum);
            sq_sum = fmaf(d2, d2, sq_sum);
        }
    }

    // ---- warp + block reduction ----
    #pragma unroll
    for (int off = 16; off > 0; off >>= 1) {
        abs_sum += __shfl_down_sync(0xFFFFFFFFu, abs_sum, off);
        sq_sum  += __shfl_down_sync(0xFFFFFFFFu, sq_sum,  off);
    }
    if (lid == 0) { s_abs[wid] = abs_sum; s_sq[wid] = sq_sum; }
    __syncthreads();

    // ---- publish partial, detect last block ----
    if (tid == 0) {
        float ba = 0.0f, bs = 0.0f;
        #pragma unroll
        for (int w = 0; w < THREADS / 32; w++) { ba += s_abs[w]; bs += s_sq[w]; }
        g_part_abs[blockIdx.x] = ba;
        g_part_sq[blockIdx.x]  = bs;
        __threadfence();
        unsigned int v = atomicInc(&g_count, N_BLOCKS - 1); // wraps to 0 on last
        s_last = (v == N_BLOCKS - 1);
    }
    __syncthreads();

    // ---- last block: final reduction over all partials (L2-resident) ----
    if (s_last) {
        double a = 0.0, s = 0.0;
        for (int i = tid; i < N_BLOCKS; i += THREADS) {
            a += (double)g_part_abs[i];
            s += (double)g_part_sq[i];
        }
        #pragma unroll
        for (int off = 16; off > 0; off >>= 1) {
            a += __shfl_down_sync(0xFFFFFFFFu, a, off);
            s += __shfl_down_sync(0xFFFFFFFFu, s, off);
        }
        __shared__ double sh_a[THREADS / 32], sh_s[THREADS / 32];
        if (lid == 0) { sh_a[wid] = a; sh_s[wid] = s; }
        __syncthreads();
        if (tid == 0) {
            double ta = 0.0, ts = 0.0;
            #pragma unroll
            for (int w = 0; w < THREADS / 32; w++) { ta += sh_a[w]; ts += sh_s[w]; }
            const double N = (double)TOTAL_ROWS * (double)ROW;
            out[0] = (float)((ta / N + 0.1 * (ts / N)) * 0.1);
        }
    }
}

extern "C" void kernel_launch(void* const* d_in, const int* in_sizes, int n_in,
                              void* d_out, int out_size) {
    const float* preds   = (const float*)d_in[0];
    const float* targets = (const float*)d_in[1];
    float* out = (float*)d_out;

    bone_loss_kernel<<<N_BLOCKS, THREADS>>>(preds, targets, out);
}

// round 4
// speedup vs baseline: 1.0567x; 1.0567x over previous
#include <cuda_runtime.h>
#include <math.h>

#define N_JOINTS 50
#define ROW 150
#define ROWS_PER_BLK 32
#define THREADS 256
#define TOTAL_ROWS (128 * 1024)
#define N_BLOCKS (TOTAL_ROWS / ROWS_PER_BLK)      // 4096
#define ELEMS (ROWS_PER_BLK * ROW)                // 4800 floats per tensor per block
#define VECS (ELEMS / 4)                          // 1200 float4

// Per-block partials, fully overwritten every launch.
__device__ float g_part_abs[N_BLOCKS];
__device__ float g_part_sq[N_BLOCKS];
// atomicInc wraps to 0 after N_BLOCKS increments -> deterministic across replays.
__device__ unsigned int g_count = 0;

__global__ __launch_bounds__(THREADS) void bone_loss_kernel(
    const float* __restrict__ preds,
    const float* __restrict__ targets,
    float* __restrict__ out)
{
    __shared__ float sp[ELEMS];
    __shared__ float st[ELEMS];
    __shared__ float s_abs[THREADS / 32];
    __shared__ float s_sq[THREADS / 32];
    __shared__ bool s_last;

    const int tid = threadIdx.x;
    const int wid = tid >> 5;
    const int lid = tid & 31;

    // ---- Phase 1: vectorized load + mask + stage to SMEM + L1 term ----
    const long long vbase = (long long)blockIdx.x * VECS;
    const float4* __restrict__ p4 = (const float4*)preds + vbase;
    const float4* __restrict__ t4 = (const float4*)targets + vbase;
    float4* sp4 = (float4*)sp;
    float4* st4 = (float4*)st;

    float abs_sum = 0.0f;
    #pragma unroll
    for (int i = tid; i < VECS; i += THREADS) {
        float4 t = __ldg(t4 + i);
        float4 p = __ldg(p4 + i);
        float4 pm;
        pm.x = (t.x != 0.0f) ? p.x : 0.0f;
        pm.y = (t.y != 0.0f) ? p.y : 0.0f;
        pm.z = (t.z != 0.0f) ? p.z : 0.0f;
        pm.w = (t.w != 0.0f) ? p.w : 0.0f;
        sp4[i] = pm;
        st4[i] = t;  // t is already 0 exactly where mask==0
        abs_sum += fabsf(pm.x - t.x) + fabsf(pm.y - t.y)
                 + fabsf(pm.z - t.z) + fabsf(pm.w - t.w);
    }
    __syncthreads();

    // ---- Phase 2: per-bone direction terms ----
    // Warp wid owns rows [4*wid, 4*wid+4); flatten 4*50 = 200 bones over 32 lanes.
    float sq_sum = 0.0f;
    const int rbase = wid * 4;
    for (int idx = lid; idx < 4 * N_JOINTS; idx += 32) {
        const int r  = idx / N_JOINTS;
        const int bi = idx - r * N_JOINTS;
        const int roff = (rbase + r) * ROW;
        const int a = roff + 3 * bi;
        const int b = roff + 3 * ((bi + 1 == N_JOINTS) ? 0 : (bi + 1));

        float pd0 = sp[a]     - sp[b];
        float pd1 = sp[a + 1] - sp[b + 1];
        float pd2 = sp[a + 2] - sp[b + 2];
        float ta0 = st[a], ta1 = st[a + 1], ta2 = st[a + 2];
        float td0 = ta0 - st[b];
        float td1 = ta1 - st[b + 1];
        float td2 = ta2 - st[b + 2];

        float pdot = fmaf(pd0, pd0, fmaf(pd1, pd1, pd2 * pd2));
        float tdot = fmaf(td0, td0, fmaf(td1, td1, td2 * td2));
        // 1/(sqrt(d)+tiny): for d>0, rsqrt(d) matches to ~3ulp; for d==0 the
        // diffs are all 0 so any finite pinv gives direction 0 — use 0.
        float pinv = (pdot > 0.0f) ? rsqrtf(pdot) : 0.0f;
        float tinv = (tdot > 0.0f) ? rsqrtf(tdot) : 0.0f;

        float d0 = (ta0 != 0.0f) ? (pd0 * pinv - td0 * tinv) : 0.0f;
        float d1 = (ta1 != 0.0f) ? (pd1 * pinv - td1 * tinv) : 0.0f;
        float d2 = (ta2 != 0.0f) ? (pd2 * pinv - td2 * tinv) : 0.0f;

        sq_sum = fmaf(d0, d0, sq_sum);
        sq_sum = fmaf(d1, d1, sq_sum);
        sq_sum = fmaf(d2, d2, sq_sum);
    }

    // ---- warp + block reduction ----
    #pragma unroll
    for (int off = 16; off > 0; off >>= 1) {
        abs_sum += __shfl_down_sync(0xFFFFFFFFu, abs_sum, off);
        sq_sum  += __shfl_down_sync(0xFFFFFFFFu, sq_sum,  off);
    }
    if (lid == 0) { s_abs[wid] = abs_sum; s_sq[wid] = sq_sum; }
    __syncthreads();

    // ---- publish partial, detect last block ----
    if (tid == 0) {
        float ba = 0.0f, bs = 0.0f;
        #pragma unroll
        for (int w = 0; w < THREADS / 32; w++) { ba += s_abs[w]; bs += s_sq[w]; }
        g_part_abs[blockIdx.x] = ba;
        g_part_sq[blockIdx.x]  = bs;
        __threadfence();
        unsigned int v = atomicInc(&g_count, N_BLOCKS - 1); // wraps to 0 on last
        s_last = (v == N_BLOCKS - 1);
    }
    __syncthreads();

    // ---- last block: final reduction over all partials (L2-resident) ----
    if (s_last) {
        double a = 0.0, s = 0.0;
        for (int i = tid; i < N_BLOCKS; i += THREADS) {
            a += (double)g_part_abs[i];
            s += (double)g_part_sq[i];
        }
        #pragma unroll
        for (int off = 16; off > 0; off >>= 1) {
            a += __shfl_down_sync(0xFFFFFFFFu, a, off);
            s += __shfl_down_sync(0xFFFFFFFFu, s, off);
        }
        __shared__ double sh_a[THREADS / 32], sh_s[THREADS / 32];
        if (lid == 0) { sh_a[wid] = a; sh_s[wid] = s; }
        __syncthreads();
        if (tid == 0) {
            double ta = 0.0, ts = 0.0;
            #pragma unroll
            for (int w = 0; w < THREADS / 32; w++) { ta += sh_a[w]; ts += sh_s[w]; }
            const double N = (double)TOTAL_ROWS * (double)ROW;
            out[0] = (float)((ta / N + 0.1 * (ts / N)) * 0.1);
        }
    }
}

extern "C" void kernel_launch(void* const* d_in, const int* in_sizes, int n_in,
                              void* d_out, int out_size) {
    const float* preds   = (const float*)d_in[0];
    const float* targets = (const float*)d_in[1];
    float* out = (float*)d_out;

    bone_loss_kernel<<<N_BLOCKS, THREADS>>>(preds, targets, out);
}